// round 12
// baseline (speedup 1.0000x reference)
#include <cuda_runtime.h>
#include <cuda_fp16.h>
#include <math.h>
#include <stdint.h>

#define TKN 768
#define NBATCH 64
#define NP 196
#define TT 197
#define RTOT (NBATCH*TT)     // 12608
#define RPACK (NBATCH*NP)    // 12544
#define NH 12
#define QKD 64
#define HN 3072
#define BETA 0.125f
#define EPS 1e-5f
#define QLD 1536
#define KDG 4608             // fused dg reduction dim: 1536 (qk) + 3072 (hopfield)
#define NGU 4608             // fused producer output dim: 1536 (q|k) + 3072 (u)

// ---------------- scratch ----------------
__device__ float  g_t   [RTOT*TKN];
__device__ __half g_g16 [RTOT*TKN];          // also reused as x16 for encode
__device__ __half g_qk16[RTOT*QLD];
__device__ __half g_au  [(size_t)RTOT*KDG];  // [oq|ok (1536) | u (3072)] per row
__device__ __half g_h16 [RPACK*TKN];
__device__ __half g_WencT16[TKN*TKN];
__device__ __half g_WdecT16[TKN*TKN];
__device__ __half g_Bgu16 [(size_t)2*NGU*TKN];  // [zq|zk|h, d] rows, K-major
__device__ __half g_Bdg16 [(size_t)2*TKN*KDG];  // [d, zq|zk|h] rows, K-major
__device__ float  g_zero4[4];                   // zero bias landing pad (unused)

static __device__ __forceinline__ uint32_t s2u(const void* p) {
    uint32_t a;
    asm("{ .reg .u64 t; cvta.to.shared.u64 t, %1; cvt.u32.u64 %0, t; }" : "=r"(a) : "l"(p));
    return a;
}

static __device__ __forceinline__ void ldm4(uint32_t* r, uint32_t addr) {
    asm volatile("ldmatrix.sync.aligned.m8n8.x4.shared.b16 {%0,%1,%2,%3}, [%4];"
                 : "=r"(r[0]), "=r"(r[1]), "=r"(r[2]), "=r"(r[3]) : "r"(addr));
}

static __device__ __forceinline__ void mma16(float* d, const uint32_t* a,
                                             uint32_t b0, uint32_t b1) {
    asm volatile(
        "mma.sync.aligned.m16n8k16.row.col.f32.f16.f16.f32 "
        "{%0,%1,%2,%3}, {%4,%5,%6,%7}, {%8,%9}, {%0,%1,%2,%3};"
        : "+f"(d[0]), "+f"(d[1]), "+f"(d[2]), "+f"(d[3])
        : "r"(a[0]), "r"(a[1]), "r"(a[2]), "r"(a[3]), "r"(b0), "r"(b1));
}

#define CPASYNC(d, s, sz) \
    asm volatile("cp.async.cg.shared.global [%0], [%1], 16, %2;" \
                 :: "r"(d), "l"(s), "r"(sz) : "memory")
#define CPCOMMIT() asm volatile("cp.async.commit_group;" ::: "memory")
#define CPWAIT0()  asm volatile("cp.async.wait_group 0;" ::: "memory")

// ---------------- fp16 mma.sync GEMM, cp.async pair-pipelined ----------------
// C[M,N] = A[M,K] @ B^T (+bias)(relu), A/B __half row-major [.,K]/[N,K]. K % 64 == 0.
// Two 32-K chunks per barrier. Smem rows: 32 halves (64B) at stride 80B.
// HOUT: half C. UPD: C(fp32) += softplus(bias[0])*acc. ENC: row-remap +pos(aux).
// GU: cols<QLD -> Cv half ldc=QLD; cols>=QLD -> relu -> Dv half ldc=KDG.
#define ROWH 40
#define OPBYTES (128*ROWH*2)       // 10240 bytes per operand
#define STAGEB (2*OPBYTES)         // 20480 per chunk slot
#define NSTAGE 4
#define GEMM_SMEM (NSTAGE*STAGEB)  // 81920

template<int RELU, int BIAS, int HOUT, int UPD, int ENC, int GU>
__global__ void __launch_bounds__(256, 2) hgemm(
    const __half* __restrict__ A, int lda,
    const __half* __restrict__ Bm, int ldb,
    void* __restrict__ Cv, int ldc,
    int M, int K, const float* __restrict__ bias, const float* __restrict__ aux,
    void* __restrict__ Dv)
{
    extern __shared__ __half smh[];
    const uint32_t sbase = s2u(smh);
    const int tid  = threadIdx.x;
    const int warp = tid >> 5, lane = tid & 31;
    const int gid  = lane >> 2, tig = lane & 3;
    const int wm = (warp & 1) * 64;
    const int wn = (warp >> 1) * 32;
    const int m0 = blockIdx.y * 128, n0 = blockIdx.x * 128;

    const bool isA  = tid < 128;
    const int  lrow = isA ? tid : tid - 128;
    const int  arow = m0 + lrow;
    const __half* lsrc = isA ? A + (size_t)(arow < M ? arow : M - 1) * lda
                             : Bm + (size_t)(n0 + lrow) * ldb;
    const uint32_t ssz  = (isA && arow >= M) ? 0u : 16u;
    const uint32_t sdst = sbase + (isA ? 0u : (uint32_t)OPBYTES) + (uint32_t)lrow * 80u;

    const uint32_t a_off = (uint32_t)(wm + (lane & 15)) * 80u + ((lane >> 4) & 1) * 16u;
    const uint32_t b_off = (uint32_t)(wn + (lane & 7) + ((lane >> 4) & 1) * 8) * 80u
                         + ((lane >> 3) & 1) * 16u + OPBYTES;

    float acc[4][4][4];
#pragma unroll
    for (int mt = 0; mt < 4; mt++)
#pragma unroll
        for (int nt = 0; nt < 4; nt++)
#pragma unroll
            for (int i = 0; i < 4; i++) acc[mt][nt][i] = 0.f;

    const int NI = K >> 6;   // 64-K pairs

#define ISSUE(chunk, slot) do { \
    uint32_t _d = sdst + (uint32_t)(slot) * (uint32_t)STAGEB; \
    const char* _s = (const char*)(lsrc + (chunk) * 32); \
    CPASYNC(_d,       _s,      ssz); CPASYNC(_d + 16u, _s + 16, ssz); \
    CPASYNC(_d + 32u, _s + 32, ssz); CPASYNC(_d + 48u, _s + 48, ssz); } while (0)

    // prologue: pair 0 -> slots 0,1
    ISSUE(0, 0); ISSUE(1, 1);
    CPCOMMIT();

    for (int i = 0; i < NI; i++) {
        CPWAIT0();            // pair i landed
        __syncthreads();      // all warps done with pair i-1 -> its slots reusable
        if (i + 1 < NI) {
            int s0 = ((i + 1) & 1) * 2;
            ISSUE(2 * i + 2, s0); ISSUE(2 * i + 3, s0 + 1);
            CPCOMMIT();
        }
        const uint32_t sP = sbase + (uint32_t)((i & 1) * 2) * STAGEB;
#pragma unroll
        for (int hf = 0; hf < 2; hf++) {
            const uint32_t sA = sP + (uint32_t)hf * STAGEB;
#pragma unroll
            for (int ks = 0; ks < 2; ks++) {
                uint32_t a[4][4], b[2][4];
#pragma unroll
                for (int mt = 0; mt < 4; mt++)
                    ldm4(a[mt], sA + a_off + mt * 1280u + ks * 32u);
#pragma unroll
                for (int np = 0; np < 2; np++)
                    ldm4(b[np], sA + b_off + np * 1280u + ks * 32u);
#pragma unroll
                for (int mt = 0; mt < 4; mt++)
#pragma unroll
                    for (int nt = 0; nt < 4; nt++)
                        mma16(acc[mt][nt], a[mt], b[nt >> 1][(nt & 1) * 2],
                              b[nt >> 1][(nt & 1) * 2 + 1]);
            }
        }
    }
#undef ISSUE

    // epilogue
    float av = 0.f;
    if (UPD) {
        float ar = bias[0];
        av = (ar > 20.f) ? ar : log1pf(expf(ar));
    }
#pragma unroll
    for (int mt = 0; mt < 4; mt++) {
        int r0 = m0 + wm + mt * 16 + gid;
        int r1 = r0 + 8;
#pragma unroll
        for (int nt = 0; nt < 4; nt++) {
            int ccol = n0 + wn + nt * 8 + tig * 2;
            float2 v0 = make_float2(acc[mt][nt][0], acc[mt][nt][1]);
            float2 v1 = make_float2(acc[mt][nt][2], acc[mt][nt][3]);
            if (BIAS) {
                float bx = bias[ccol], by = bias[ccol + 1];
                v0.x += bx; v0.y += by; v1.x += bx; v1.y += by;
            }
            if (RELU) {
                v0.x = fmaxf(v0.x, 0.f); v0.y = fmaxf(v0.y, 0.f);
                v1.x = fmaxf(v1.x, 0.f); v1.y = fmaxf(v1.y, 0.f);
            }
            if (GU) {
                if (n0 < QLD) {
                    __half* C = (__half*)Cv;
                    if (r0 < M) *(__half2*)&C[(size_t)r0 * QLD + ccol] = __floats2half2_rn(v0.x, v0.y);
                    if (r1 < M) *(__half2*)&C[(size_t)r1 * QLD + ccol] = __floats2half2_rn(v1.x, v1.y);
                } else {
                    __half* D = (__half*)Dv;
                    v0.x = fmaxf(v0.x, 0.f); v0.y = fmaxf(v0.y, 0.f);
                    v1.x = fmaxf(v1.x, 0.f); v1.y = fmaxf(v1.y, 0.f);
                    if (r0 < M) *(__half2*)&D[(size_t)r0 * KDG + ccol] = __floats2half2_rn(v0.x, v0.y);
                    if (r1 < M) *(__half2*)&D[(size_t)r1 * KDG + ccol] = __floats2half2_rn(v1.x, v1.y);
                }
            } else if (ENC) {
                float* C = (float*)Cv;
                if (r0 < M) {
                    int bb = r0 / NP, tok = r0 - bb * NP + 1;
                    float2 p = *(const float2*)&aux[(size_t)tok * TKN + ccol];
                    v0.x += p.x; v0.y += p.y;
                    *(float2*)&C[(size_t)(bb * TT + tok) * ldc + ccol] = v0;
                }
                if (r1 < M) {
                    int bb = r1 / NP, tok = r1 - bb * NP + 1;
                    float2 p = *(const float2*)&aux[(size_t)tok * TKN + ccol];
                    v1.x += p.x; v1.y += p.y;
                    *(float2*)&C[(size_t)(bb * TT + tok) * ldc + ccol] = v1;
                }
            } else if (UPD) {
                float* C = (float*)Cv;
                if (r0 < M) {
                    float2* p = (float2*)&C[(size_t)r0 * ldc + ccol];
                    float2 o = *p;
                    o.x += av * v0.x; o.y += av * v0.y;
                    *p = o;
                }
                if (r1 < M) {
                    float2* p = (float2*)&C[(size_t)r1 * ldc + ccol];
                    float2 o = *p;
                    o.x += av * v1.x; o.y += av * v1.y;
                    *p = o;
                }
            } else if (HOUT) {
                __half* C = (__half*)Cv;
                if (r0 < M) *(__half2*)&C[(size_t)r0 * ldc + ccol] = __floats2half2_rn(v0.x, v0.y);
                if (r1 < M) *(__half2*)&C[(size_t)r1 * ldc + ccol] = __floats2half2_rn(v1.x, v1.y);
            } else {
                float* C = (float*)Cv;
                if (r0 < M) *(float2*)&C[(size_t)r0 * ldc + ccol] = v0;
                if (r1 < M) *(float2*)&C[(size_t)r1 * ldc + ccol] = v1;
            }
        }
    }
}

// ---------------- fused weight prep: fp32 -> fp16, optional transpose ----------------
struct PTask { const float* s; __half* d; int cols, ldd, coff, trans, tbase; };
struct PArgs { PTask t[16]; int n; };

__global__ void prep_kernel(PArgs pa)
{
    __shared__ float tile[32][33];
    int bid = blockIdx.x;
    int ti = 0;
#pragma unroll 1
    for (int i = 1; i < pa.n; i++)
        if (pa.t[i].tbase <= bid) ti = i;
    PTask tk = pa.t[ti];
    int rel = bid - tk.tbase;
    int ctiles = tk.cols >> 5;
    int r0 = (rel / ctiles) << 5, c0 = (rel % ctiles) << 5;
    int x = threadIdx.x, y = threadIdx.y;
#pragma unroll
    for (int yy = 0; yy < 4; yy++)
        tile[y + 8 * yy][x] = tk.s[(size_t)(r0 + y + 8 * yy) * tk.cols + c0 + x];
    __syncthreads();
    if (tk.trans) {
#pragma unroll
        for (int yy = 0; yy < 4; yy++)
            tk.d[(size_t)(c0 + y + 8 * yy) * tk.ldd + tk.coff + r0 + x] =
                __float2half_rn(tile[x][y + 8 * yy]);
    } else {
#pragma unroll
        for (int yy = 0; yy < 4; yy++)
            tk.d[(size_t)(r0 + y + 8 * yy) * tk.ldd + tk.coff + c0 + x] =
                __float2half_rn(tile[y + 8 * yy][x]);
    }
}

// ---------------- CLS rows: t[b*197, :] = cls + pos[0] ----------------
__global__ void clsfill_kernel(const float* __restrict__ cls, const float* __restrict__ pos,
                               float* __restrict__ t)
{
    int j = blockIdx.y * 256 + threadIdx.x;
    t[(size_t)blockIdx.x * TT * TKN + j] = cls[j] + pos[j];
}

// ---------------- reductions ----------------
__device__ __forceinline__ float block_reduce_sum(float v) {
    __shared__ float sh[8];
    int lane = threadIdx.x & 31, w = threadIdx.x >> 5;
#pragma unroll
    for (int o = 16; o; o >>= 1) v += __shfl_xor_sync(0xffffffffu, v, o);
    if (lane == 0) sh[w] = v;
    __syncthreads();
    if (w == 0) {
        float r = (lane < 8) ? sh[lane] : 0.f;
#pragma unroll
        for (int o = 4; o; o >>= 1) r += __shfl_xor_sync(0xffffffffu, r, o);
        if (lane == 0) sh[0] = r;
    }
    __syncthreads();
    float r = sh[0];
    __syncthreads();
    return r;
}

// ---------------- EnergyLayerNorm: writes half ----------------
__global__ void enorm_kernel(const float* __restrict__ t, __half* __restrict__ g,
                             const float* __restrict__ gamma, const float* __restrict__ bias,
                             int blk)
{
    int row = blockIdx.x;
    const float* x = t + (size_t)row * TKN;
    __half* o = g + (size_t)row * TKN;
    int tid = threadIdx.x;

    float v[3];
    float s = 0.f;
#pragma unroll
    for (int i = 0; i < 3; i++) { v[i] = x[tid + 256 * i]; s += v[i]; }
    s = block_reduce_sum(s);
    float mu = s * (1.f / 768.f);

    float ss = 0.f;
#pragma unroll
    for (int i = 0; i < 3; i++) { v[i] -= mu; ss += v[i] * v[i]; }
    ss = block_reduce_sum(ss);
    float r = rsqrtf(ss * (1.f / 768.f) + EPS) * gamma[blk];

#pragma unroll
    for (int i = 0; i < 3; i++)
        o[tid + 256 * i] = __float2half_rn(v[i] * r + bias[blk * TKN + tid + 256 * i]);
}

// ---------------- decode LayerNorm: writes half ----------------
__global__ void decln_kernel(const float* __restrict__ t, __half* __restrict__ h,
                             const float* __restrict__ ln_g, const float* __restrict__ ln_b)
{
    int m = blockIdx.x;
    int row = (m / NP) * TT + (m % NP) + 1;
    const float* x = t + (size_t)row * TKN;
    __half* o = h + (size_t)m * TKN;
    int tid = threadIdx.x;

    float v[3];
    float s = 0.f;
#pragma unroll
    for (int i = 0; i < 3; i++) { v[i] = x[tid + 256 * i]; s += v[i]; }
    s = block_reduce_sum(s);
    float mu = s * (1.f / 768.f);

    float ss = 0.f;
#pragma unroll
    for (int i = 0; i < 3; i++) { v[i] -= mu; ss += v[i] * v[i]; }
    ss = block_reduce_sum(ss);
    float r = rsqrtf(ss * (1.f / 768.f) + EPS);

#pragma unroll
    for (int i = 0; i < 3; i++) {
        int j = tid + 256 * i;
        o[j] = __float2half_rn(v[i] * r * ln_g[j] + ln_b[j]);
    }
}

// ---------------- fused attention: qk16 in, oq|ok -> au cols 0..1535 ----------------
#define KSTRIDE 68
#define RBSTRIDE 200
#define ATTN_SMEM_BYTES ((2*TT*KSTRIDE + 8*RBSTRIDE + 2*TT) * 4)

__global__ void __launch_bounds__(256) attn_kernel(
    const __half* __restrict__ qk, __half* __restrict__ au)
{
    extern __shared__ float sm[];
    float* Qs   = sm;
    float* Ks   = Qs + TT * KSTRIDE;
    float* bufA = Ks + TT * KSTRIDE;
    float* rmax = bufA + 8 * RBSTRIDE;
    float* rinv = rmax + TT;

    int bh = blockIdx.x;
    int b = bh / NH, h = bh % NH;
    const __half* qb = qk + (size_t)b * TT * QLD + h * QKD;
    const __half* kb = qb + 768;
    int tid = threadIdx.x, lane = tid & 31, w = tid >> 5;

    for (int idx = tid; idx < TT * 32; idx += 256) {
        int i = idx >> 5, z2 = (idx & 31) * 2;
        float2 qf = __half22float2(*(const __half2*)&qb[(size_t)i * QLD + z2]);
        float2 kf = __half22float2(*(const __half2*)&kb[(size_t)i * QLD + z2]);
        Qs[i * KSTRIDE + z2] = qf.x; Qs[i * KSTRIDE + z2 + 1] = qf.y;
        Ks[i * KSTRIDE + z2] = kf.x; Ks[i * KSTRIDE + z2 + 1] = kf.y;
    }
    __syncthreads();

    float* rb = bufA + w * RBSTRIDE;

    // pass 1: oq = A K, cache (rmax, rinv)
    for (int i = w; i < TT; i += 8) {
        const float* Qi = Qs + i * KSTRIDE;
        float lmax = -1e30f;
        for (int j = lane; j < TT; j += 32) {
            const float* Kj = Ks + j * KSTRIDE;
            float d = 0.f;
#pragma unroll
            for (int z4 = 0; z4 < 16; z4++) {
                float4 qv = *reinterpret_cast<const float4*>(&Qi[z4 * 4]);
                float4 kv = *reinterpret_cast<const float4*>(&Kj[z4 * 4]);
                d += qv.x * kv.x + qv.y * kv.y + qv.z * kv.z + qv.w * kv.w;
            }
            d *= BETA;
            rb[j] = d;
            lmax = fmaxf(lmax, d);
        }
#pragma unroll
        for (int o = 16; o; o >>= 1) lmax = fmaxf(lmax, __shfl_xor_sync(0xffffffffu, lmax, o));
        float lsum = 0.f;
        for (int j = lane; j < TT; j += 32) {
            float e = __expf(rb[j] - lmax);
            rb[j] = e;
            lsum += e;
        }
#pragma unroll
        for (int o = 16; o; o >>= 1) lsum += __shfl_xor_sync(0xffffffffu, lsum, o);
        float inv = 1.f / lsum;
        if (lane == 0) { rmax[i] = lmax; rinv[i] = inv; }
        __syncwarp();

        float a0 = 0.f, a1 = 0.f;
        for (int j4 = 0; j4 < 49; j4++) {
            float4 e4 = *reinterpret_cast<const float4*>(&rb[j4 * 4]);
            int j = j4 * 4;
            a0 += e4.x * Ks[(j + 0) * KSTRIDE + lane] + e4.y * Ks[(j + 1) * KSTRIDE + lane]
                + e4.z * Ks[(j + 2) * KSTRIDE + lane] + e4.w * Ks[(j + 3) * KSTRIDE + lane];
            a1 += e4.x * Ks[(j + 0) * KSTRIDE + 32 + lane] + e4.y * Ks[(j + 1) * KSTRIDE + 32 + lane]
                + e4.z * Ks[(j + 2) * KSTRIDE + 32 + lane] + e4.w * Ks[(j + 3) * KSTRIDE + 32 + lane];
        }
        {
            float e = rb[196];
            a0 += e * Ks[196 * KSTRIDE + lane];
            a1 += e * Ks[196 * KSTRIDE + 32 + lane];
        }
        __half* od = au + (size_t)(b * TT + i) * KDG + h * QKD;
        od[lane] = __float2half_rn(a0 * inv);
        od[lane + 32] = __float2half_rn(a1 * inv);
    }
    __syncthreads();

    // pass 2: ok = A^T Q
    for (int j = w; j < TT; j += 8) {
        const float* Kj = Ks + j * KSTRIDE;
        for (int i = lane; i < TT; i += 32) {
            const float* Qi = Qs + i * KSTRIDE;
            float d = 0.f;
#pragma unroll
            for (int z4 = 0; z4 < 16; z4++) {
                float4 qv = *reinterpret_cast<const float4*>(&Qi[z4 * 4]);
                float4 kv = *reinterpret_cast<const float4*>(&Kj[z4 * 4]);
                d += qv.x * kv.x + qv.y * kv.y + qv.z * kv.z + qv.w * kv.w;
            }
            rb[i] = __expf(d * BETA - rmax[i]) * rinv[i];
        }
        __syncwarp();

        float a0 = 0.f, a1 = 0.f;
        for (int i4 = 0; i4 < 49; i4++) {
            float4 e4 = *reinterpret_cast<const float4*>(&rb[i4 * 4]);
            int i = i4 * 4;
            a0 += e4.x * Qs[(i + 0) * KSTRIDE + lane] + e4.y * Qs[(i + 1) * KSTRIDE + lane]
                + e4.z * Qs[(i + 2) * KSTRIDE + lane] + e4.w * Qs[(i + 3) * KSTRIDE + lane];
            a1 += e4.x * Qs[(i + 0) * KSTRIDE + 32 + lane] + e4.y * Qs[(i + 1) * KSTRIDE + 32 + lane]
                + e4.z * Qs[(i + 2) * KSTRIDE + 32 + lane] + e4.w * Qs[(i + 3) * KSTRIDE + 32 + lane];
        }
        {
            float e = rb[196];
            a0 += e * Qs[196 * KSTRIDE + lane];
            a1 += e * Qs[196 * KSTRIDE + 32 + lane];
        }
        __half* od = au + (size_t)(b * TT + j) * KDG + 768 + h * QKD;
        od[lane] = __float2half_rn(a0);
        od[lane + 32] = __float2half_rn(a1);
    }
}

// ---------------- host orchestration ----------------
extern "C" void kernel_launch(void* const* d_in, const int* in_sizes, int n_in,
                              void* d_out, int out_size)
{
    const float* x         = (const float*)d_in[0];
    const float* W_enc     = (const float*)d_in[1];
    const float* b_enc     = (const float*)d_in[2];
    const float* cls       = (const float*)d_in[3];
    const float* pos       = (const float*)d_in[4];
    const float* gamma     = (const float*)d_in[5];
    const float* bias      = (const float*)d_in[6];
    const float* Wq        = (const float*)d_in[7];
    const float* Wk        = (const float*)d_in[8];
    const float* Whn       = (const float*)d_in[9];
    const float* alpha_raw = (const float*)d_in[10];
    const float* ln_g      = (const float*)d_in[11];
    const float* ln_b      = (const float*)d_in[12];
    const float* W_dec     = (const float*)d_in[13];
    const float* b_dec     = (const float*)d_in[14];
    float* out = (float*)d_out;

    float* t;
    __half *g16, *qk16, *au, *h16, *WencT16, *WdecT16, *Bgu16, *Bdg16;
    cudaGetSymbolAddress((void**)&t,    g_t);
    cudaGetSymbolAddress((void**)&g16,  g_g16);
    cudaGetSymbolAddress((void**)&qk16, g_qk16);
    cudaGetSymbolAddress((void**)&au,   g_au);
    cudaGetSymbolAddress((void**)&h16,  g_h16);
    cudaGetSymbolAddress((void**)&WencT16, g_WencT16);
    cudaGetSymbolAddress((void**)&WdecT16, g_WdecT16);
    cudaGetSymbolAddress((void**)&Bgu16,   g_Bgu16);
    cudaGetSymbolAddress((void**)&Bdg16,   g_Bdg16);

    cudaFuncSetAttribute(attn_kernel, cudaFuncAttributeMaxDynamicSharedMemorySize,
                         ATTN_SMEM_BYTES);
    cudaFuncSetAttribute(hgemm<0, 1, 0, 0, 1, 0>, cudaFuncAttributeMaxDynamicSharedMemorySize, GEMM_SMEM);
    cudaFuncSetAttribute(hgemm<0, 0, 0, 0, 0, 1>, cudaFuncAttributeMaxDynamicSharedMemorySize, GEMM_SMEM);
    cudaFuncSetAttribute(hgemm<0, 0, 0, 1, 0, 0>, cudaFuncAttributeMaxDynamicSharedMemorySize, GEMM_SMEM);
    cudaFuncSetAttribute(hgemm<0, 1, 0, 0, 0, 0>, cudaFuncAttributeMaxDynamicSharedMemorySize, GEMM_SMEM);

    // ---- fused weight/input prep (single launch) ----
    PArgs pa;
    int nt = 0, tb = 0;
    auto add = [&](const float* s, __half* d, int rows, int cols, int ldd, int coff, int tr) {
        pa.t[nt].s = s; pa.t[nt].d = d; pa.t[nt].cols = cols; pa.t[nt].ldd = ldd;
        pa.t[nt].coff = coff; pa.t[nt].trans = tr; pa.t[nt].tbase = tb;
        tb += (rows / 32) * (cols / 32);
        nt++;
    };
    add(x, g16, RPACK, TKN, TKN, 0, 0);                      // x -> half (g16 reused)
    add(W_enc, WencT16, TKN, TKN, TKN, 0, 1);
    add(W_dec, WdecT16, TKN, TKN, TKN, 0, 1);
    for (int blk = 0; blk < 2; blk++) {
        const float* Wq_b  = Wq  + (size_t)blk * TKN * TKN;
        const float* Wk_b  = Wk  + (size_t)blk * TKN * TKN;
        const float* Whn_b = Whn + (size_t)blk * TKN * HN;
        __half* Bgu_b = Bgu16 + (size_t)blk * NGU * TKN;
        __half* Bdg_b = Bdg16 + (size_t)blk * TKN * KDG;
        add(Wq_b,  Bgu_b,                       TKN, TKN, TKN, 0, 0);  // rows 0..767
        add(Wk_b,  Bgu_b + (size_t)TKN * TKN,   TKN, TKN, TKN, 0, 0);  // rows 768..1535
        add(Whn_b, Bgu_b + (size_t)QLD * TKN,   TKN, HN,  TKN, 0, 1);  // rows 1536..4607 (WhnT)
        add(Wq_b,  Bdg_b, TKN, TKN, KDG, 0,   1);
        add(Wk_b,  Bdg_b, TKN, TKN, KDG, TKN, 1);
        add(Whn_b, Bdg_b, TKN, HN,  KDG, QLD, 0);
    }
    pa.n = nt;
    prep_kernel<<<tb, dim3(32, 8)>>>(pa);                                   // 0

    // ---- encode straight into t (+pos, row remap), then CLS rows ----
    hgemm<0, 1, 0, 0, 1, 0><<<dim3(6, RPACK / 128), 256, GEMM_SMEM>>>(      // 1
        g16, TKN, WencT16, TKN, t, TKN, RPACK, TKN, b_enc, pos, nullptr);
    clsfill_kernel<<<dim3(NBATCH, 3), 256>>>(cls, pos, t);                  // 2

    const int MT = (RTOT + 127) / 128;   // 99

    for (int blk = 0; blk < 2; blk++) {
        const __half* Bgu_b = Bgu16 + (size_t)blk * NGU * TKN;
        const __half* Bdg_b = Bdg16 + (size_t)blk * TKN * KDG;
        for (int s = 0; s < 4; s++) {
            enorm_kernel<<<RTOT, 256>>>(t, g16, gamma, bias, blk);          // 3
            // [qk | u] = g @ Bgu^T : cols<1536 -> qk16, cols>=1536 -> relu -> au
            hgemm<0, 0, 0, 0, 0, 1><<<dim3(36, MT), 256, GEMM_SMEM>>>(      // 4
                g16, TKN, Bgu_b, TKN, qk16, QLD, RTOT, TKN, nullptr, nullptr, au);
            // attention -> au cols 0..1535
            attn_kernel<<<NBATCH * NH, 256, ATTN_SMEM_BYTES>>>(qk16, au);   // 5
            // t += softplus(alpha) * (au @ Bdg^T)   (K = 4608, fused update)
            hgemm<0, 0, 0, 1, 0, 0><<<dim3(6, MT), 256, GEMM_SMEM>>>(
                au, KDG, Bdg_b, KDG, t, TKN, RTOT, KDG, alpha_raw + blk, nullptr, nullptr);
        }
    }

    // ---- decode ----
    decln_kernel<<<RPACK, 256>>>(t, h16, ln_g, ln_b);
    hgemm<0, 1, 0, 0, 0, 0><<<dim3(6, RPACK / 128), 256, GEMM_SMEM>>>(
        h16, TKN, WdecT16, TKN, out, TKN, RPACK, TKN, b_dec, nullptr, nullptr);
}

// round 13
// speedup vs baseline: 1.1636x; 1.1636x over previous
#include <cuda_runtime.h>
#include <cuda_fp16.h>
#include <math.h>
#include <stdint.h>

#define TKN 768
#define NBATCH 64
#define NP 196
#define TT 197
#define RTOT (NBATCH*TT)     // 12608
#define RPACK (NBATCH*NP)    // 12544
#define NH 12
#define QKD 64
#define HN 3072
#define BETA 0.125f
#define EPS 1e-5f
#define QLD 1536
#define KDG 4608             // fused dg reduction dim: 1536 (qk) + 3072 (hopfield)

// ---------------- scratch ----------------
__device__ float  g_t   [RTOT*TKN];
__device__ __half g_g16 [RTOT*TKN];          // also reused as x16 for encode
__device__ __half g_qk16[RTOT*QLD];
__device__ __half g_au  [(size_t)RTOT*KDG];  // [oq|ok (1536) | u (3072)] per row
__device__ __half g_h16 [RPACK*TKN];
__device__ __half g_WencT16[TKN*TKN];
__device__ __half g_WdecT16[TKN*TKN];
__device__ __half g_Bqk16 [2*QLD*TKN];       // [z|z', d]
__device__ __half g_Bdg16 [(size_t)2*TKN*KDG]; // [d, zq|zk|h]
__device__ __half g_WhnT16[(size_t)2*HN*TKN];

static __device__ __forceinline__ uint32_t s2u(const void* p) {
    uint32_t a;
    asm("{ .reg .u64 t; cvta.to.shared.u64 t, %1; cvt.u32.u64 %0, t; }" : "=r"(a) : "l"(p));
    return a;
}

static __device__ __forceinline__ void ldm4(uint32_t* r, uint32_t addr) {
    asm volatile("ldmatrix.sync.aligned.m8n8.x4.shared.b16 {%0,%1,%2,%3}, [%4];"
                 : "=r"(r[0]), "=r"(r[1]), "=r"(r[2]), "=r"(r[3]) : "r"(addr));
}

static __device__ __forceinline__ void mma16(float* d, const uint32_t* a,
                                             uint32_t b0, uint32_t b1) {
    asm volatile(
        "mma.sync.aligned.m16n8k16.row.col.f32.f16.f16.f32 "
        "{%0,%1,%2,%3}, {%4,%5,%6,%7}, {%8,%9}, {%0,%1,%2,%3};"
        : "+f"(d[0]), "+f"(d[1]), "+f"(d[2]), "+f"(d[3])
        : "r"(a[0]), "r"(a[1]), "r"(a[2]), "r"(a[3]), "r"(b0), "r"(b1));
}

#define CPASYNC(d, s, sz) \
    asm volatile("cp.async.cg.shared.global [%0], [%1], 16, %2;" \
                 :: "r"(d), "l"(s), "r"(sz) : "memory")
#define CPCOMMIT() asm volatile("cp.async.commit_group;" ::: "memory")
#define CPWAIT2()  asm volatile("cp.async.wait_group 2;" ::: "memory")

// ---------------- fp16 mma.sync GEMM, cp.async 4-stage pipeline (R11 proven) ----------------
// C[M,N] = A[M,K] @ B^T (+bias)(relu), A/B __half row-major [.,K]/[N,K].
// CTA tile 128x128, K-chunk 32. Smem rows: 32 halves (64B) at stride 80B.
// HOUT: write __half C. UPD: C(fp32) += softplus(bias[0]) * acc.
// ENC: C(fp32)=t with row remap (b*197+tok+1) and +pos (aux) +bias.
#define ROWH 40
#define OPBYTES (128*ROWH*2)       // 10240 bytes per operand
#define STAGEB (2*OPBYTES)         // 20480 per stage
#define NSTAGE 4
#define GEMM_SMEM (NSTAGE*STAGEB)  // 81920

template<int RELU, int BIAS, int HOUT, int UPD, int ENC>
__global__ void __launch_bounds__(256, 2) hgemm(
    const __half* __restrict__ A, int lda,
    const __half* __restrict__ Bm, int ldb,
    void* __restrict__ Cv, int ldc,
    int M, int K, const float* __restrict__ bias, const float* __restrict__ aux)
{
    extern __shared__ __half smh[];
    const uint32_t sbase = s2u(smh);
    const int tid  = threadIdx.x;
    const int warp = tid >> 5, lane = tid & 31;
    const int gid  = lane >> 2, tig = lane & 3;
    const int wm = (warp & 1) * 64;
    const int wn = (warp >> 1) * 32;
    const int m0 = blockIdx.y * 128, n0 = blockIdx.x * 128;

    const bool isA  = tid < 128;
    const int  lrow = isA ? tid : tid - 128;
    const int  arow = m0 + lrow;
    const __half* lsrc = isA ? A + (size_t)(arow < M ? arow : M - 1) * lda
                             : Bm + (size_t)(n0 + lrow) * ldb;
    const uint32_t ssz  = (isA && arow >= M) ? 0u : 16u;
    const uint32_t sdst = sbase + (isA ? 0u : (uint32_t)OPBYTES) + (uint32_t)lrow * 80u;

    const uint32_t a_off = (uint32_t)(wm + (lane & 15)) * 80u + ((lane >> 4) & 1) * 16u;
    const uint32_t b_off = (uint32_t)(wn + (lane & 7) + ((lane >> 4) & 1) * 8) * 80u
                         + ((lane >> 3) & 1) * 16u + OPBYTES;

    float acc[4][4][4];
#pragma unroll
    for (int mt = 0; mt < 4; mt++)
#pragma unroll
        for (int nt = 0; nt < 4; nt++)
#pragma unroll
            for (int i = 0; i < 4; i++) acc[mt][nt][i] = 0.f;

    const int NC = K >> 5;

#define ISSUE(chunk, slot) do { \
    uint32_t _d = sdst + (uint32_t)(slot) * (uint32_t)STAGEB; \
    const char* _s = (const char*)(lsrc + (chunk) * 32); \
    CPASYNC(_d,       _s,      ssz); CPASYNC(_d + 16u, _s + 16, ssz); \
    CPASYNC(_d + 32u, _s + 32, ssz); CPASYNC(_d + 48u, _s + 48, ssz); } while (0)

    if (0 < NC) ISSUE(0, 0);
    CPCOMMIT();
    if (1 < NC) ISSUE(1, 1);
    CPCOMMIT();
    if (2 < NC) ISSUE(2, 2);
    CPCOMMIT();

    for (int c = 0; c < NC; c++) {
        CPWAIT2();
        __syncthreads();
        int nxt = c + 3;
        if (nxt < NC) ISSUE(nxt, nxt & 3);
        CPCOMMIT();

        const uint32_t sA = sbase + (uint32_t)(c & 3) * STAGEB;
#pragma unroll
        for (int ks = 0; ks < 2; ks++) {
            uint32_t a[4][4], b[2][4];
#pragma unroll
            for (int mt = 0; mt < 4; mt++)
                ldm4(a[mt], sA + a_off + mt * 1280u + ks * 32u);
#pragma unroll
            for (int np = 0; np < 2; np++)
                ldm4(b[np], sA + b_off + np * 1280u + ks * 32u);
#pragma unroll
            for (int mt = 0; mt < 4; mt++)
#pragma unroll
                for (int nt = 0; nt < 4; nt++)
                    mma16(acc[mt][nt], a[mt], b[nt >> 1][(nt & 1) * 2],
                          b[nt >> 1][(nt & 1) * 2 + 1]);
        }
    }
#undef ISSUE

    // epilogue
    float av = 0.f;
    if (UPD) {
        float ar = bias[0];
        av = (ar > 20.f) ? ar : log1pf(expf(ar));
    }
#pragma unroll
    for (int mt = 0; mt < 4; mt++) {
        int r0 = m0 + wm + mt * 16 + gid;
        int r1 = r0 + 8;
#pragma unroll
        for (int nt = 0; nt < 4; nt++) {
            int ccol = n0 + wn + nt * 8 + tig * 2;
            float2 v0 = make_float2(acc[mt][nt][0], acc[mt][nt][1]);
            float2 v1 = make_float2(acc[mt][nt][2], acc[mt][nt][3]);
            if (BIAS) {
                float bx = bias[ccol], by = bias[ccol + 1];
                v0.x += bx; v0.y += by; v1.x += bx; v1.y += by;
            }
            if (RELU) {
                v0.x = fmaxf(v0.x, 0.f); v0.y = fmaxf(v0.y, 0.f);
                v1.x = fmaxf(v1.x, 0.f); v1.y = fmaxf(v1.y, 0.f);
            }
            if (ENC) {
                float* C = (float*)Cv;
                if (r0 < M) {
                    int bb = r0 / NP, tok = r0 - bb * NP + 1;
                    float2 p = *(const float2*)&aux[(size_t)tok * TKN + ccol];
                    v0.x += p.x; v0.y += p.y;
                    *(float2*)&C[(size_t)(bb * TT + tok) * ldc + ccol] = v0;
                }
                if (r1 < M) {
                    int bb = r1 / NP, tok = r1 - bb * NP + 1;
                    float2 p = *(const float2*)&aux[(size_t)tok * TKN + ccol];
                    v1.x += p.x; v1.y += p.y;
                    *(float2*)&C[(size_t)(bb * TT + tok) * ldc + ccol] = v1;
                }
            } else if (UPD) {
                float* C = (float*)Cv;
                if (r0 < M) {
                    float2* p = (float2*)&C[(size_t)r0 * ldc + ccol];
                    float2 o = *p;
                    o.x += av * v0.x; o.y += av * v0.y;
                    *p = o;
                }
                if (r1 < M) {
                    float2* p = (float2*)&C[(size_t)r1 * ldc + ccol];
                    float2 o = *p;
                    o.x += av * v1.x; o.y += av * v1.y;
                    *p = o;
                }
            } else if (HOUT) {
                __half* C = (__half*)Cv;
                if (r0 < M) *(__half2*)&C[(size_t)r0 * ldc + ccol] = __floats2half2_rn(v0.x, v0.y);
                if (r1 < M) *(__half2*)&C[(size_t)r1 * ldc + ccol] = __floats2half2_rn(v1.x, v1.y);
            } else {
                float* C = (float*)Cv;
                if (r0 < M) *(float2*)&C[(size_t)r0 * ldc + ccol] = v0;
                if (r1 < M) *(float2*)&C[(size_t)r1 * ldc + ccol] = v1;
            }
        }
    }
}

// ---------------- fused weight prep: fp32 -> fp16, optional transpose ----------------
struct PTask { const float* s; __half* d; int cols, ldd, coff, trans, tbase; };
struct PArgs { PTask t[16]; int n; };

__global__ void prep_kernel(PArgs pa)
{
    __shared__ float tile[32][33];
    int bid = blockIdx.x;
    int ti = 0;
#pragma unroll 1
    for (int i = 1; i < pa.n; i++)
        if (pa.t[i].tbase <= bid) ti = i;
    PTask tk = pa.t[ti];
    int rel = bid - tk.tbase;
    int ctiles = tk.cols >> 5;
    int r0 = (rel / ctiles) << 5, c0 = (rel % ctiles) << 5;
    int x = threadIdx.x, y = threadIdx.y;
#pragma unroll
    for (int yy = 0; yy < 4; yy++)
        tile[y + 8 * yy][x] = tk.s[(size_t)(r0 + y + 8 * yy) * tk.cols + c0 + x];
    __syncthreads();
    if (tk.trans) {
#pragma unroll
        for (int yy = 0; yy < 4; yy++)
            tk.d[(size_t)(c0 + y + 8 * yy) * tk.ldd + tk.coff + r0 + x] =
                __float2half_rn(tile[x][y + 8 * yy]);
    } else {
#pragma unroll
        for (int yy = 0; yy < 4; yy++)
            tk.d[(size_t)(r0 + y + 8 * yy) * tk.ldd + tk.coff + c0 + x] =
                __float2half_rn(tile[y + 8 * yy][x]);
    }
}

// ---------------- CLS rows: t[b*197, :] = cls + pos[0] ----------------
__global__ void clsfill_kernel(const float* __restrict__ cls, const float* __restrict__ pos,
                               float* __restrict__ t)
{
    int j = blockIdx.y * 256 + threadIdx.x;
    t[(size_t)blockIdx.x * TT * TKN + j] = cls[j] + pos[j];
}

// ---------------- reductions ----------------
__device__ __forceinline__ float block_reduce_sum(float v) {
    __shared__ float sh[8];
    int lane = threadIdx.x & 31, w = threadIdx.x >> 5;
#pragma unroll
    for (int o = 16; o; o >>= 1) v += __shfl_xor_sync(0xffffffffu, v, o);
    if (lane == 0) sh[w] = v;
    __syncthreads();
    if (w == 0) {
        float r = (lane < 8) ? sh[lane] : 0.f;
#pragma unroll
        for (int o = 4; o; o >>= 1) r += __shfl_xor_sync(0xffffffffu, r, o);
        if (lane == 0) sh[0] = r;
    }
    __syncthreads();
    float r = sh[0];
    __syncthreads();
    return r;
}

// ---------------- EnergyLayerNorm: writes half ----------------
__global__ void enorm_kernel(const float* __restrict__ t, __half* __restrict__ g,
                             const float* __restrict__ gamma, const float* __restrict__ bias,
                             int blk)
{
    int row = blockIdx.x;
    const float* x = t + (size_t)row * TKN;
    __half* o = g + (size_t)row * TKN;
    int tid = threadIdx.x;

    float v[3];
    float s = 0.f;
#pragma unroll
    for (int i = 0; i < 3; i++) { v[i] = x[tid + 256 * i]; s += v[i]; }
    s = block_reduce_sum(s);
    float mu = s * (1.f / 768.f);

    float ss = 0.f;
#pragma unroll
    for (int i = 0; i < 3; i++) { v[i] -= mu; ss += v[i] * v[i]; }
    ss = block_reduce_sum(ss);
    float r = rsqrtf(ss * (1.f / 768.f) + EPS) * gamma[blk];

#pragma unroll
    for (int i = 0; i < 3; i++)
        o[tid + 256 * i] = __float2half_rn(v[i] * r + bias[blk * TKN + tid + 256 * i]);
}

// ---------------- decode LayerNorm: writes half ----------------
__global__ void decln_kernel(const float* __restrict__ t, __half* __restrict__ h,
                             const float* __restrict__ ln_g, const float* __restrict__ ln_b)
{
    int m = blockIdx.x;
    int row = (m / NP) * TT + (m % NP) + 1;
    const float* x = t + (size_t)row * TKN;
    __half* o = h + (size_t)m * TKN;
    int tid = threadIdx.x;

    float v[3];
    float s = 0.f;
#pragma unroll
    for (int i = 0; i < 3; i++) { v[i] = x[tid + 256 * i]; s += v[i]; }
    s = block_reduce_sum(s);
    float mu = s * (1.f / 768.f);

    float ss = 0.f;
#pragma unroll
    for (int i = 0; i < 3; i++) { v[i] -= mu; ss += v[i] * v[i]; }
    ss = block_reduce_sum(ss);
    float r = rsqrtf(ss * (1.f / 768.f) + EPS);

#pragma unroll
    for (int i = 0; i < 3; i++) {
        int j = tid + 256 * i;
        o[j] = __float2half_rn(v[i] * r * ln_g[j] + ln_b[j]);
    }
}

// ---------------- fused attention: qk16 in, oq|ok -> au cols 0..1535 ----------------
#define KSTRIDE 68
#define RBSTRIDE 200
#define ATTN_SMEM_BYTES ((2*TT*KSTRIDE + 8*RBSTRIDE + 2*TT) * 4)

__global__ void __launch_bounds__(256) attn_kernel(
    const __half* __restrict__ qk, __half* __restrict__ au)
{
    extern __shared__ float sm[];
    float* Qs   = sm;
    float* Ks   = Qs + TT * KSTRIDE;
    float* bufA = Ks + TT * KSTRIDE;
    float* rmax = bufA + 8 * RBSTRIDE;
    float* rinv = rmax + TT;

    int bh = blockIdx.x;
    int b = bh / NH, h = bh % NH;
    const __half* qb = qk + (size_t)b * TT * QLD + h * QKD;
    const __half* kb = qb + 768;
    int tid = threadIdx.x, lane = tid & 31, w = tid >> 5;

    for (int idx = tid; idx < TT * 32; idx += 256) {
        int i = idx >> 5, z2 = (idx & 31) * 2;
        float2 qf = __half22float2(*(const __half2*)&qb[(size_t)i * QLD + z2]);
        float2 kf = __half22float2(*(const __half2*)&kb[(size_t)i * QLD + z2]);
        Qs[i * KSTRIDE + z2] = qf.x; Qs[i * KSTRIDE + z2 + 1] = qf.y;
        Ks[i * KSTRIDE + z2] = kf.x; Ks[i * KSTRIDE + z2 + 1] = kf.y;
    }
    __syncthreads();

    float* rb = bufA + w * RBSTRIDE;

    // pass 1: oq = A K, cache (rmax, rinv)
    for (int i = w; i < TT; i += 8) {
        const float* Qi = Qs + i * KSTRIDE;
        float lmax = -1e30f;
        for (int j = lane; j < TT; j += 32) {
            const float* Kj = Ks + j * KSTRIDE;
            float d = 0.f;
#pragma unroll
            for (int z4 = 0; z4 < 16; z4++) {
                float4 qv = *reinterpret_cast<const float4*>(&Qi[z4 * 4]);
                float4 kv = *reinterpret_cast<const float4*>(&Kj[z4 * 4]);
                d += qv.x * kv.x + qv.y * kv.y + qv.z * kv.z + qv.w * kv.w;
            }
            d *= BETA;
            rb[j] = d;
            lmax = fmaxf(lmax, d);
        }
#pragma unroll
        for (int o = 16; o; o >>= 1) lmax = fmaxf(lmax, __shfl_xor_sync(0xffffffffu, lmax, o));
        float lsum = 0.f;
        for (int j = lane; j < TT; j += 32) {
            float e = __expf(rb[j] - lmax);
            rb[j] = e;
            lsum += e;
        }
#pragma unroll
        for (int o = 16; o; o >>= 1) lsum += __shfl_xor_sync(0xffffffffu, lsum, o);
        float inv = 1.f / lsum;
        if (lane == 0) { rmax[i] = lmax; rinv[i] = inv; }
        __syncwarp();

        float a0 = 0.f, a1 = 0.f;
        for (int j4 = 0; j4 < 49; j4++) {
            float4 e4 = *reinterpret_cast<const float4*>(&rb[j4 * 4]);
            int j = j4 * 4;
            a0 += e4.x * Ks[(j + 0) * KSTRIDE + lane] + e4.y * Ks[(j + 1) * KSTRIDE + lane]
                + e4.z * Ks[(j + 2) * KSTRIDE + lane] + e4.w * Ks[(j + 3) * KSTRIDE + lane];
            a1 += e4.x * Ks[(j + 0) * KSTRIDE + 32 + lane] + e4.y * Ks[(j + 1) * KSTRIDE + 32 + lane]
                + e4.z * Ks[(j + 2) * KSTRIDE + 32 + lane] + e4.w * Ks[(j + 3) * KSTRIDE + 32 + lane];
        }
        {
            float e = rb[196];
            a0 += e * Ks[196 * KSTRIDE + lane];
            a1 += e * Ks[196 * KSTRIDE + 32 + lane];
        }
        __half* od = au + (size_t)(b * TT + i) * KDG + h * QKD;
        od[lane] = __float2half_rn(a0 * inv);
        od[lane + 32] = __float2half_rn(a1 * inv);
    }
    __syncthreads();

    // pass 2: ok = A^T Q
    for (int j = w; j < TT; j += 8) {
        const float* Kj = Ks + j * KSTRIDE;
        for (int i = lane; i < TT; i += 32) {
            const float* Qi = Qs + i * KSTRIDE;
            float d = 0.f;
#pragma unroll
            for (int z4 = 0; z4 < 16; z4++) {
                float4 qv = *reinterpret_cast<const float4*>(&Qi[z4 * 4]);
                float4 kv = *reinterpret_cast<const float4*>(&Kj[z4 * 4]);
                d += qv.x * kv.x + qv.y * kv.y + qv.z * kv.z + qv.w * kv.w;
            }
            rb[i] = __expf(d * BETA - rmax[i]) * rinv[i];
        }
        __syncwarp();

        float a0 = 0.f, a1 = 0.f;
        for (int i4 = 0; i4 < 49; i4++) {
            float4 e4 = *reinterpret_cast<const float4*>(&rb[i4 * 4]);
            int i = i4 * 4;
            a0 += e4.x * Qs[(i + 0) * KSTRIDE + lane] + e4.y * Qs[(i + 1) * KSTRIDE + lane]
                + e4.z * Qs[(i + 2) * KSTRIDE + lane] + e4.w * Qs[(i + 3) * KSTRIDE + lane];
            a1 += e4.x * Qs[(i + 0) * KSTRIDE + 32 + lane] + e4.y * Qs[(i + 1) * KSTRIDE + 32 + lane]
                + e4.z * Qs[(i + 2) * KSTRIDE + 32 + lane] + e4.w * Qs[(i + 3) * KSTRIDE + 32 + lane];
        }
        {
            float e = rb[196];
            a0 += e * Qs[196 * KSTRIDE + lane];
            a1 += e * Qs[196 * KSTRIDE + 32 + lane];
        }
        __half* od = au + (size_t)(b * TT + j) * KDG + 768 + h * QKD;
        od[lane] = __float2half_rn(a0);
        od[lane + 32] = __float2half_rn(a1);
    }
}

// ---------------- host orchestration ----------------
extern "C" void kernel_launch(void* const* d_in, const int* in_sizes, int n_in,
                              void* d_out, int out_size)
{
    const float* x         = (const float*)d_in[0];
    const float* W_enc     = (const float*)d_in[1];
    const float* b_enc     = (const float*)d_in[2];
    const float* cls       = (const float*)d_in[3];
    const float* pos       = (const float*)d_in[4];
    const float* gamma     = (const float*)d_in[5];
    const float* bias      = (const float*)d_in[6];
    const float* Wq        = (const float*)d_in[7];
    const float* Wk        = (const float*)d_in[8];
    const float* Whn       = (const float*)d_in[9];
    const float* alpha_raw = (const float*)d_in[10];
    const float* ln_g      = (const float*)d_in[11];
    const float* ln_b      = (const float*)d_in[12];
    const float* W_dec     = (const float*)d_in[13];
    const float* b_dec     = (const float*)d_in[14];
    float* out = (float*)d_out;

    float* t;
    __half *g16, *qk16, *au, *h16, *WencT16, *WdecT16, *Bqk16, *Bdg16, *WhnT16;
    cudaGetSymbolAddress((void**)&t,    g_t);
    cudaGetSymbolAddress((void**)&g16,  g_g16);
    cudaGetSymbolAddress((void**)&qk16, g_qk16);
    cudaGetSymbolAddress((void**)&au,   g_au);
    cudaGetSymbolAddress((void**)&h16,  g_h16);
    cudaGetSymbolAddress((void**)&WencT16, g_WencT16);
    cudaGetSymbolAddress((void**)&WdecT16, g_WdecT16);
    cudaGetSymbolAddress((void**)&Bqk16,   g_Bqk16);
    cudaGetSymbolAddress((void**)&Bdg16,   g_Bdg16);
    cudaGetSymbolAddress((void**)&WhnT16,  g_WhnT16);

    // side stream + fork/join events, created once (host bookkeeping only —
    // enqueued GPU work is identical on every call; stream must outlive graph
    // capture, so it is never destroyed here)
    static cudaStream_t s2 = nullptr;
    static cudaEvent_t ev_fork = nullptr, ev_join = nullptr;
    if (s2 == nullptr) {
        cudaStreamCreateWithFlags(&s2, cudaStreamNonBlocking);
        cudaEventCreateWithFlags(&ev_fork, cudaEventDisableTiming);
        cudaEventCreateWithFlags(&ev_join, cudaEventDisableTiming);
    }

    cudaFuncSetAttribute(attn_kernel, cudaFuncAttributeMaxDynamicSharedMemorySize,
                         ATTN_SMEM_BYTES);
    cudaFuncSetAttribute(hgemm<0, 1, 0, 0, 1>, cudaFuncAttributeMaxDynamicSharedMemorySize, GEMM_SMEM);
    cudaFuncSetAttribute(hgemm<0, 0, 1, 0, 0>, cudaFuncAttributeMaxDynamicSharedMemorySize, GEMM_SMEM);
    cudaFuncSetAttribute(hgemm<1, 0, 1, 0, 0>, cudaFuncAttributeMaxDynamicSharedMemorySize, GEMM_SMEM);
    cudaFuncSetAttribute(hgemm<0, 0, 0, 1, 0>, cudaFuncAttributeMaxDynamicSharedMemorySize, GEMM_SMEM);
    cudaFuncSetAttribute(hgemm<0, 1, 0, 0, 0>, cudaFuncAttributeMaxDynamicSharedMemorySize, GEMM_SMEM);

    // ---- fused weight/input prep (single launch) ----
    PArgs pa;
    int nt = 0, tb = 0;
    auto add = [&](const float* s, __half* d, int rows, int cols, int ldd, int coff, int tr) {
        pa.t[nt].s = s; pa.t[nt].d = d; pa.t[nt].cols = cols; pa.t[nt].ldd = ldd;
        pa.t[nt].coff = coff; pa.t[nt].trans = tr; pa.t[nt].tbase = tb;
        tb += (rows / 32) * (cols / 32);
        nt++;
    };
    add(x, g16, RPACK, TKN, TKN, 0, 0);                      // x -> half (g16 reused)
    add(W_enc, WencT16, TKN, TKN, TKN, 0, 1);
    add(W_dec, WdecT16, TKN, TKN, TKN, 0, 1);
    for (int blk = 0; blk < 2; blk++) {
        const float* Wq_b  = Wq  + (size_t)blk * TKN * TKN;
        const float* Wk_b  = Wk  + (size_t)blk * TKN * TKN;
        const float* Whn_b = Whn + (size_t)blk * TKN * HN;
        __half* Bdg_b = Bdg16 + (size_t)blk * TKN * KDG;
        add(Wq_b, Bqk16 + (size_t)blk * QLD * TKN, TKN, TKN, TKN, 0, 0);
        add(Wk_b, Bqk16 + (size_t)blk * QLD * TKN + TKN * TKN, TKN, TKN, TKN, 0, 0);
        add(Wq_b, Bdg_b, TKN, TKN, KDG, 0, 1);
        add(Wk_b, Bdg_b, TKN, TKN, KDG, TKN, 1);
        add(Whn_b, Bdg_b, TKN, HN, KDG, QLD, 0);
        add(Whn_b, WhnT16 + (size_t)blk * HN * TKN, TKN, HN, TKN, 0, 1);
    }
    pa.n = nt;
    prep_kernel<<<tb, dim3(32, 8)>>>(pa);                                   // 0

    // ---- encode straight into t (+pos, row remap), then CLS rows ----
    hgemm<0, 1, 0, 0, 1><<<dim3(6, RPACK / 128), 256, GEMM_SMEM>>>(         // 1
        g16, TKN, WencT16, TKN, t, TKN, RPACK, TKN, b_enc, pos);
    clsfill_kernel<<<dim3(NBATCH, 3), 256>>>(cls, pos, t);                  // 2

    const int MT = (RTOT + 127) / 128;   // 99

    for (int blk = 0; blk < 2; blk++) {
        const __half* Bqk_b  = Bqk16  + (size_t)blk * QLD * TKN;
        const __half* Bdg_b  = Bdg16  + (size_t)blk * TKN * KDG;
        const __half* WhnT_b = WhnT16 + (size_t)blk * HN * TKN;
        for (int s = 0; s < 4; s++) {
            enorm_kernel<<<RTOT, 256>>>(t, g16, gamma, bias, blk);          // 3
            // qk = g @ [Wq;Wk]^T -> half [RTOT,1536]
            hgemm<0, 0, 1, 0, 0><<<dim3(12, MT), 256, GEMM_SMEM>>>(         // 4
                g16, TKN, Bqk_b, TKN, qk16, QLD, RTOT, TKN, nullptr, nullptr);
            // fork: attention on s2 (reads qk16, writes au cols 0..1535)
            cudaEventRecord(ev_fork, 0);
            cudaStreamWaitEvent(s2, ev_fork, 0);
            attn_kernel<<<NBATCH * NH, 256, ATTN_SMEM_BYTES, s2>>>(qk16, au);
            // main stream: u = relu(g @ Whn) -> au cols 1536..4607 (independent)
            hgemm<1, 0, 1, 0, 0><<<dim3(24, MT), 256, GEMM_SMEM>>>(
                g16, TKN, WhnT_b, TKN, au + QLD, KDG, RTOT, TKN, nullptr, nullptr);
            // join
            cudaEventRecord(ev_join, s2);
            cudaStreamWaitEvent(0, ev_join, 0);
            // t += softplus(alpha) * (au @ Bdg^T)   (K = 4608, fused update)
            hgemm<0, 0, 0, 1, 0><<<dim3(6, MT), 256, GEMM_SMEM>>>(
                au, KDG, Bdg_b, KDG, t, TKN, RTOT, KDG, alpha_raw + blk, nullptr);
        }
    }

    // ---- decode ----
    decln_kernel<<<RPACK, 256>>>(t, h16, ln_g, ln_b);
    hgemm<0, 1, 0, 0, 0><<<dim3(6, RPACK / 128), 256, GEMM_SMEM>>>(
        h16, TKN, WdecT16, TKN, out, TKN, RPACK, TKN, b_dec, nullptr);
}